// round 3
// baseline (speedup 1.0000x reference)
#include <cuda_runtime.h>

#define N_NODES 100000
#define E_EDGES 1600000
#define TOT_E   (E_EDGES + N_NODES)
#define INC 128
#define OUTC 64
#define LRELU_ALPHA 0.2f

// Scratch (static device arrays -- runtime allocation is forbidden).
__device__ __align__(16) float g_h[(size_t)N_NODES * OUTC];    // 25.6 MB
__device__ __align__(16) float g_acc[(size_t)N_NODES * OUTC];  // 25.6 MB
__device__ float g_s[N_NODES];
__device__ float g_t[N_NODES];
__device__ float g_expsum[N_NODES];
__device__ int   g_idx64;   // 1 if edge_index is int64-layout, 0 if int32

// ---------------------------------------------------------------------------
// Detect index dtype: int64 little-endian with values < N has all-zero odd
// 32-bit words; genuine int32 data has random values there (P[all 64 zero]
// ~ 1e-320). Deterministic, graph-capturable, ~1us.
// ---------------------------------------------------------------------------
__global__ void detect_kernel(const int* __restrict__ ei32) {
    int allzero = 1;
#pragma unroll 1
    for (int k = 0; k < 64; ++k)
        if (ei32[2 * k + 1] != 0) { allzero = 0; break; }
    g_idx64 = allzero;
}

// ---------------------------------------------------------------------------
__global__ void zero_kernel() {
    int i = blockIdx.x * blockDim.x + threadIdx.x;
    if (i < N_NODES * OUTC) g_acc[i] = 0.0f;
    if (i < N_NODES) g_expsum[i] = 0.0f;
}

// ---------------------------------------------------------------------------
// h = x @ W (fp32), fused with s = h.a1, t = h.a2. One thread per node row.
// ---------------------------------------------------------------------------
__global__ __launch_bounds__(256) void gemm_kernel(
    const float* __restrict__ x, const float* __restrict__ W,
    const float* __restrict__ a)
{
    int row = blockIdx.x * blockDim.x + threadIdx.x;
    if (row >= N_NODES) return;

    float acc[OUTC];
#pragma unroll
    for (int c = 0; c < OUTC; ++c) acc[c] = 0.0f;

    const float4* xr = reinterpret_cast<const float4*>(x + (size_t)row * INC);
#pragma unroll 2
    for (int k4 = 0; k4 < INC / 4; ++k4) {
        float4 xv = __ldg(xr + k4);
        float xk[4] = {xv.x, xv.y, xv.z, xv.w};
#pragma unroll
        for (int kk = 0; kk < 4; ++kk) {
            const float4* w4 =
                reinterpret_cast<const float4*>(W + (size_t)(k4 * 4 + kk) * OUTC);
#pragma unroll
            for (int c4 = 0; c4 < OUTC / 4; ++c4) {
                float4 wv = __ldg(w4 + c4);
                acc[c4 * 4 + 0] = fmaf(xk[kk], wv.x, acc[c4 * 4 + 0]);
                acc[c4 * 4 + 1] = fmaf(xk[kk], wv.y, acc[c4 * 4 + 1]);
                acc[c4 * 4 + 2] = fmaf(xk[kk], wv.z, acc[c4 * 4 + 2]);
                acc[c4 * 4 + 3] = fmaf(xk[kk], wv.w, acc[c4 * 4 + 3]);
            }
        }
    }

    float s = 0.0f, t = 0.0f;
#pragma unroll
    for (int c = 0; c < OUTC; ++c) {
        s = fmaf(acc[c], __ldg(a + c), s);
        t = fmaf(acc[c], __ldg(a + OUTC + c), t);
    }

    float4* hp = reinterpret_cast<float4*>(g_h + (size_t)row * OUTC);
#pragma unroll
    for (int c4 = 0; c4 < OUTC / 4; ++c4)
        hp[c4] = make_float4(acc[c4 * 4 + 0], acc[c4 * 4 + 1],
                             acc[c4 * 4 + 2], acc[c4 * 4 + 3]);
    g_s[row] = s;
    g_t[row] = t;
}

// ---------------------------------------------------------------------------
// Edge phase: one warp per edge (incl. N self-loops appended at the end).
// ---------------------------------------------------------------------------
__global__ __launch_bounds__(256) void edge_kernel(const void* __restrict__ ei)
{
    int gwarp = (blockIdx.x * blockDim.x + threadIdx.x) >> 5;
    int lane = threadIdx.x & 31;
    int nwarps = (gridDim.x * blockDim.x) >> 5;
    const int is64 = g_idx64;
    const int* ei32 = (const int*)ei;
    const long long* ei64 = (const long long*)ei;

    for (int e = gwarp; e < TOT_E; e += nwarps) {
        int src, dst;
        if (e < E_EDGES) {
            if (is64) {
                src = (int)__ldg(ei64 + e);
                dst = (int)__ldg(ei64 + E_EDGES + e);
            } else {
                src = __ldg(ei32 + e);
                dst = __ldg(ei32 + E_EDGES + e);
            }
        } else {
            src = e - E_EDGES;
            dst = src;
        }
        float z = __ldg(g_s + src) + __ldg(g_t + dst);
        float lr = (z > 0.0f) ? z : LRELU_ALPHA * z;
        float w = __expf(lr);

        const float* hd = g_h + (size_t)dst * OUTC;
        float* os = g_acc + (size_t)src * OUTC;

        atomicAdd(os + lane,      w * __ldg(hd + lane));
        atomicAdd(os + lane + 32, w * __ldg(hd + lane + 32));
        if (lane == 0) atomicAdd(g_expsum + src, w);
    }
}

// ---------------------------------------------------------------------------
__global__ void finalize_kernel(float* __restrict__ out) {
    int i = blockIdx.x * blockDim.x + threadIdx.x;
    if (i < N_NODES * OUTC) {
        out[i] = g_acc[i] / g_expsum[i >> 6];
    }
}

// ---------------------------------------------------------------------------
extern "C" void kernel_launch(void* const* d_in, const int* in_sizes, int n_in,
                              void* d_out, int out_size)
{
    const float* x = (const float*)d_in[0];
    const float* W = (const float*)d_in[1];
    const float* a = (const float*)d_in[2];
    const void*  ei = d_in[3];
    float* out = (float*)d_out;

    const int nz = (N_NODES * OUTC + 255) / 256;

    detect_kernel<<<1, 1>>>((const int*)ei);
    zero_kernel<<<nz, 256>>>();
    gemm_kernel<<<(N_NODES + 255) / 256, 256>>>(x, W, a);
    edge_kernel<<<1184, 256>>>(ei);
    finalize_kernel<<<nz, 256>>>(out);
}

// round 4
// speedup vs baseline: 1.4905x; 1.4905x over previous
#include <cuda_runtime.h>

#define N_NODES 100000
#define E_EDGES 1600000
#define INC 128
#define OUTC 64
#define LRELU_ALPHA 0.2f

// Scratch (static device arrays -- runtime allocation is forbidden).
__device__ __align__(16) float g_h[(size_t)N_NODES * OUTC];    // 25.6 MB
__device__ __align__(16) float g_acc[(size_t)N_NODES * OUTC];  // 25.6 MB
__device__ float g_s[N_NODES];
__device__ float g_t[N_NODES];
__device__ float g_expsum[N_NODES];
__device__ int   g_idx64;   // 1 if edge_index is int64-layout, 0 if int32

// ---------------------------------------------------------------------------
// Detect index dtype (int64 LE with values < N has all-zero odd words).
// ---------------------------------------------------------------------------
__global__ void detect_kernel(const int* __restrict__ ei32) {
    int allzero = 1;
#pragma unroll 1
    for (int k = 0; k < 64; ++k)
        if (ei32[2 * k + 1] != 0) { allzero = 0; break; }
    g_idx64 = allzero;
}

// ---------------------------------------------------------------------------
// h = x @ W (fp32) with W staged in shared memory, fused with:
//   s = h.a1, t = h.a2
//   self-loop: w = exp(lrelu(s+t)); g_acc[row] = w*h; g_expsum[row] = w
// (so no separate zero kernel and no self-loop edges in the edge kernel)
// ---------------------------------------------------------------------------
__global__ __launch_bounds__(256) void gemm_kernel(
    const float* __restrict__ x, const float* __restrict__ W,
    const float* __restrict__ a)
{
    __shared__ __align__(16) float sW[INC * OUTC];   // 32 KB

    // cooperative load of W (8192 floats, 256 threads -> 8 float4 each)
    {
        const float4* Wv = reinterpret_cast<const float4*>(W);
        float4* sWv = reinterpret_cast<float4*>(sW);
#pragma unroll
        for (int i = 0; i < (INC * OUTC) / (256 * 4); ++i)
            sWv[threadIdx.x + i * 256] = Wv[threadIdx.x + i * 256];
    }
    __syncthreads();

    int row = blockIdx.x * blockDim.x + threadIdx.x;
    if (row >= N_NODES) return;

    float acc[OUTC];
#pragma unroll
    for (int c = 0; c < OUTC; ++c) acc[c] = 0.0f;

    const float4* xr = reinterpret_cast<const float4*>(x + (size_t)row * INC);
#pragma unroll 2
    for (int k4 = 0; k4 < INC / 4; ++k4) {
        float4 xv = __ldg(xr + k4);
        float xk[4] = {xv.x, xv.y, xv.z, xv.w};
#pragma unroll
        for (int kk = 0; kk < 4; ++kk) {
            const float4* w4 =
                reinterpret_cast<const float4*>(sW + (k4 * 4 + kk) * OUTC);
#pragma unroll
            for (int c4 = 0; c4 < OUTC / 4; ++c4) {
                float4 wv = w4[c4];
                acc[c4 * 4 + 0] = fmaf(xk[kk], wv.x, acc[c4 * 4 + 0]);
                acc[c4 * 4 + 1] = fmaf(xk[kk], wv.y, acc[c4 * 4 + 1]);
                acc[c4 * 4 + 2] = fmaf(xk[kk], wv.z, acc[c4 * 4 + 2]);
                acc[c4 * 4 + 3] = fmaf(xk[kk], wv.w, acc[c4 * 4 + 3]);
            }
        }
    }

    float s = 0.0f, t = 0.0f;
#pragma unroll
    for (int c = 0; c < OUTC; ++c) {
        s = fmaf(acc[c], __ldg(a + c), s);
        t = fmaf(acc[c], __ldg(a + OUTC + c), t);
    }

    // self-loop weight
    float z = s + t;
    float lr = (z > 0.0f) ? z : LRELU_ALPHA * z;
    float w = __expf(lr);

    float4* hp = reinterpret_cast<float4*>(g_h + (size_t)row * OUTC);
    float4* ap = reinterpret_cast<float4*>(g_acc + (size_t)row * OUTC);
#pragma unroll
    for (int c4 = 0; c4 < OUTC / 4; ++c4) {
        float4 hv = make_float4(acc[c4 * 4 + 0], acc[c4 * 4 + 1],
                                acc[c4 * 4 + 2], acc[c4 * 4 + 3]);
        hp[c4] = hv;
        ap[c4] = make_float4(w * hv.x, w * hv.y, w * hv.z, w * hv.w);
    }
    g_s[row] = s;
    g_t[row] = t;
    g_expsum[row] = w;
}

// ---------------------------------------------------------------------------
// Edge phase: one warp handles TWO edges per iteration; 16 lanes per edge,
// float4 per lane. Gather of both edges' h rows = one LDG.128 warp-instr;
// accumulation = one red.global.add.v4.f32 warp-instr.
// ---------------------------------------------------------------------------
__global__ __launch_bounds__(256) void edge_kernel(const void* __restrict__ ei)
{
    const int NPAIRS = E_EDGES / 2;
    int gwarp = (blockIdx.x * blockDim.x + threadIdx.x) >> 5;
    int nwarps = (gridDim.x * blockDim.x) >> 5;
    int lane = threadIdx.x & 31;
    int half = lane >> 4;        // which of the 2 edges
    int sub  = lane & 15;        // float4 index within the 64-ch row

    const int is64 = g_idx64;
    const int* ei32 = (const int*)ei;
    const long long* ei64 = (const long long*)ei;

    for (int p = gwarp; p < NPAIRS; p += nwarps) {
        int e = 2 * p + half;
        int src, dst;
        if (is64) {
            src = (int)__ldg(ei64 + e);
            dst = (int)__ldg(ei64 + E_EDGES + e);
        } else {
            src = __ldg(ei32 + e);
            dst = __ldg(ei32 + E_EDGES + e);
        }

        float z = __ldg(g_s + src) + __ldg(g_t + dst);
        float lr = (z > 0.0f) ? z : LRELU_ALPHA * z;
        float w = __expf(lr);

        const float4* hd = reinterpret_cast<const float4*>(g_h + (size_t)dst * OUTC);
        float4 v = __ldg(hd + sub);
        float4 r = make_float4(w * v.x, w * v.y, w * v.z, w * v.w);

        float* os = g_acc + (size_t)src * OUTC + 4 * sub;
        asm volatile("red.global.add.v4.f32 [%0], {%1, %2, %3, %4};"
                     :: "l"(os), "f"(r.x), "f"(r.y), "f"(r.z), "f"(r.w)
                     : "memory");
        if (sub == 0) atomicAdd(g_expsum + src, w);
    }
}

// ---------------------------------------------------------------------------
// out = g_acc / expsum  (vectorized; plain stores to d_out only)
// ---------------------------------------------------------------------------
__global__ void finalize_kernel(float* __restrict__ out) {
    int i4 = blockIdx.x * blockDim.x + threadIdx.x;
    if (i4 < N_NODES * OUTC / 4) {
        float inv = 1.0f / g_expsum[i4 >> 4];
        float4 v = reinterpret_cast<const float4*>(g_acc)[i4];
        reinterpret_cast<float4*>(out)[i4] =
            make_float4(v.x * inv, v.y * inv, v.z * inv, v.w * inv);
    }
}

// ---------------------------------------------------------------------------
extern "C" void kernel_launch(void* const* d_in, const int* in_sizes, int n_in,
                              void* d_out, int out_size)
{
    const float* x = (const float*)d_in[0];
    const float* W = (const float*)d_in[1];
    const float* a = (const float*)d_in[2];
    const void*  ei = d_in[3];
    float* out = (float*)d_out;

    detect_kernel<<<1, 1>>>((const int*)ei);
    gemm_kernel<<<(N_NODES + 255) / 256, 256>>>(x, W, a);
    edge_kernel<<<1480, 256>>>(ei);
    finalize_kernel<<<(N_NODES * OUTC / 4 + 255) / 256, 256>>>(out);
}

// round 5
// speedup vs baseline: 1.8672x; 1.2528x over previous
#include <cuda_runtime.h>

#define N_NODES 100000
#define E_EDGES 1600000
#define INC 128
#define OUTC 64
#define LRELU_ALPHA 0.2f

#define SCAN_B 1024
#define SCAN_NBLK ((N_NODES + SCAN_B - 1) / SCAN_B)   // 98

// Static device scratch (runtime allocation forbidden)
__device__ __align__(16) float g_h[(size_t)N_NODES * OUTC];   // 25.6 MB
__device__ float g_s[N_NODES];
__device__ float g_t[N_NODES];
__device__ int   g_hist[N_NODES];
__device__ int   g_start[N_NODES];
__device__ int   g_cursor[N_NODES];
__device__ int   g_blocksum[SCAN_NBLK];
__device__ int   g_blockoff[SCAN_NBLK];
__device__ int   g_sorted_dst[E_EDGES];                        // 6.4 MB
__device__ float g_sorted_w[E_EDGES];                          // 6.4 MB
__device__ int   g_idx64;

// ---------------------------------------------------------------------------
__global__ void detect_kernel(const int* __restrict__ ei32) {
    int allzero = 1;
#pragma unroll 1
    for (int k = 0; k < 64; ++k)
        if (ei32[2 * k + 1] != 0) { allzero = 0; break; }
    g_idx64 = allzero;
}

__global__ void zero_hist_kernel() {
    int i = blockIdx.x * blockDim.x + threadIdx.x;
    if (i < N_NODES) g_hist[i] = 0;
}

// ---------------------------------------------------------------------------
// h = x @ W (W staged in smem), fused s = h.a1, t = h.a2.
// ---------------------------------------------------------------------------
__global__ __launch_bounds__(256) void gemm_kernel(
    const float* __restrict__ x, const float* __restrict__ W,
    const float* __restrict__ a)
{
    __shared__ __align__(16) float sW[INC * OUTC];   // 32 KB
    {
        const float4* Wv = reinterpret_cast<const float4*>(W);
        float4* sWv = reinterpret_cast<float4*>(sW);
#pragma unroll
        for (int i = 0; i < (INC * OUTC) / (256 * 4); ++i)
            sWv[threadIdx.x + i * 256] = Wv[threadIdx.x + i * 256];
    }
    __syncthreads();

    int row = blockIdx.x * blockDim.x + threadIdx.x;
    if (row >= N_NODES) return;

    float acc[OUTC];
#pragma unroll
    for (int c = 0; c < OUTC; ++c) acc[c] = 0.0f;

    const float4* xr = reinterpret_cast<const float4*>(x + (size_t)row * INC);
#pragma unroll 2
    for (int k4 = 0; k4 < INC / 4; ++k4) {
        float4 xv = __ldg(xr + k4);
        float xk[4] = {xv.x, xv.y, xv.z, xv.w};
#pragma unroll
        for (int kk = 0; kk < 4; ++kk) {
            const float4* w4 =
                reinterpret_cast<const float4*>(sW + (k4 * 4 + kk) * OUTC);
#pragma unroll
            for (int c4 = 0; c4 < OUTC / 4; ++c4) {
                float4 wv = w4[c4];
                acc[c4 * 4 + 0] = fmaf(xk[kk], wv.x, acc[c4 * 4 + 0]);
                acc[c4 * 4 + 1] = fmaf(xk[kk], wv.y, acc[c4 * 4 + 1]);
                acc[c4 * 4 + 2] = fmaf(xk[kk], wv.z, acc[c4 * 4 + 2]);
                acc[c4 * 4 + 3] = fmaf(xk[kk], wv.w, acc[c4 * 4 + 3]);
            }
        }
    }

    float s = 0.0f, t = 0.0f;
#pragma unroll
    for (int c = 0; c < OUTC; ++c) {
        s = fmaf(acc[c], __ldg(a + c), s);
        t = fmaf(acc[c], __ldg(a + OUTC + c), t);
    }

    float4* hp = reinterpret_cast<float4*>(g_h + (size_t)row * OUTC);
#pragma unroll
    for (int c4 = 0; c4 < OUTC / 4; ++c4)
        hp[c4] = make_float4(acc[c4 * 4 + 0], acc[c4 * 4 + 1],
                             acc[c4 * 4 + 2], acc[c4 * 4 + 3]);
    g_s[row] = s;
    g_t[row] = t;
}

// ---------------------------------------------------------------------------
// Counting sort: histogram of src
// ---------------------------------------------------------------------------
__global__ __launch_bounds__(256) void hist_kernel(const void* __restrict__ ei)
{
    int e = blockIdx.x * blockDim.x + threadIdx.x;
    if (e >= E_EDGES) return;
    int src = g_idx64 ? (int)__ldg((const long long*)ei + e)
                      : __ldg((const int*)ei + e);
    atomicAdd(g_hist + src, 1);
}

// Scan step 1: per-block exclusive scan (Hillis-Steele) + block totals
__global__ __launch_bounds__(SCAN_B) void scan1_kernel()
{
    __shared__ int sh[SCAN_B];
    int tid = threadIdx.x;
    int i = blockIdx.x * SCAN_B + tid;
    int v = (i < N_NODES) ? g_hist[i] : 0;
    sh[tid] = v;
    __syncthreads();
#pragma unroll
    for (int off = 1; off < SCAN_B; off <<= 1) {
        int t = (tid >= off) ? sh[tid - off] : 0;
        __syncthreads();
        sh[tid] += t;
        __syncthreads();
    }
    if (i < N_NODES) g_start[i] = sh[tid] - v;   // exclusive
    if (tid == SCAN_B - 1) g_blocksum[blockIdx.x] = sh[tid];
}

// Scan step 2: scan the 98 block totals (single thread, trivial)
__global__ void scan2_kernel()
{
    int run = 0;
#pragma unroll 1
    for (int b = 0; b < SCAN_NBLK; ++b) {
        g_blockoff[b] = run;
        run += g_blocksum[b];
    }
}

// Scan step 3: add block offsets; init cursor = start
__global__ __launch_bounds__(SCAN_B) void scan3_kernel()
{
    int i = blockIdx.x * SCAN_B + threadIdx.x;
    if (i < N_NODES) {
        int s = g_start[i] + g_blockoff[blockIdx.x];
        g_start[i] = s;
        g_cursor[i] = s;
    }
}

// Scatter: place (dst, w) into src-sorted arrays; w computed here.
__global__ __launch_bounds__(256) void scatter_kernel(const void* __restrict__ ei)
{
    int e = blockIdx.x * blockDim.x + threadIdx.x;
    if (e >= E_EDGES) return;
    int src, dst;
    if (g_idx64) {
        src = (int)__ldg((const long long*)ei + e);
        dst = (int)__ldg((const long long*)ei + E_EDGES + e);
    } else {
        src = __ldg((const int*)ei + e);
        dst = __ldg((const int*)ei + E_EDGES + e);
    }
    float z = __ldg(g_s + src) + __ldg(g_t + dst);
    float lr = (z > 0.0f) ? z : LRELU_ALPHA * z;
    float w = __expf(lr);

    int pos = atomicAdd(g_cursor + src, 1);
    g_sorted_dst[pos] = dst;
    g_sorted_w[pos] = w;
}

// ---------------------------------------------------------------------------
// Aggregate: 16 lanes per node (2 nodes per warp). Gather-only; writes d_out
// once (finalize + self-loop fused). No atomics.
// ---------------------------------------------------------------------------
__global__ __launch_bounds__(256) void aggregate_kernel(float* __restrict__ out)
{
    int gt = blockIdx.x * blockDim.x + threadIdx.x;
    int node = gt >> 4;
    int sub = gt & 15;            // float4 index within 64-ch row
    if (node >= N_NODES) return;

    // self-loop
    float z = __ldg(g_s + node) + __ldg(g_t + node);
    float lr = (z > 0.0f) ? z : LRELU_ALPHA * z;
    float wself = __expf(lr);

    const float4* hn = reinterpret_cast<const float4*>(g_h + (size_t)node * OUTC);
    float4 hv = __ldg(hn + sub);
    float4 acc = make_float4(wself * hv.x, wself * hv.y, wself * hv.z, wself * hv.w);
    float es = wself;

    int base = __ldg(g_start + node);
    int cnt = __ldg(g_hist + node);
#pragma unroll 2
    for (int j = 0; j < cnt; ++j) {
        int dst = __ldg(g_sorted_dst + base + j);
        float w = __ldg(g_sorted_w + base + j);
        const float4* hd = reinterpret_cast<const float4*>(g_h + (size_t)dst * OUTC);
        float4 v = __ldg(hd + sub);
        acc.x = fmaf(w, v.x, acc.x);
        acc.y = fmaf(w, v.y, acc.y);
        acc.z = fmaf(w, v.z, acc.z);
        acc.w = fmaf(w, v.w, acc.w);
        es += w;
    }

    float inv = 1.0f / es;
    reinterpret_cast<float4*>(out)[(size_t)node * 16 + sub] =
        make_float4(acc.x * inv, acc.y * inv, acc.z * inv, acc.w * inv);
}

// ---------------------------------------------------------------------------
extern "C" void kernel_launch(void* const* d_in, const int* in_sizes, int n_in,
                              void* d_out, int out_size)
{
    const float* x = (const float*)d_in[0];
    const float* W = (const float*)d_in[1];
    const float* a = (const float*)d_in[2];
    const void*  ei = d_in[3];
    float* out = (float*)d_out;

    detect_kernel<<<1, 1>>>((const int*)ei);
    zero_hist_kernel<<<(N_NODES + 255) / 256, 256>>>();
    gemm_kernel<<<(N_NODES + 255) / 256, 256>>>(x, W, a);
    hist_kernel<<<(E_EDGES + 255) / 256, 256>>>(ei);
    scan1_kernel<<<SCAN_NBLK, SCAN_B>>>();
    scan2_kernel<<<1, 1>>>();
    scan3_kernel<<<SCAN_NBLK, SCAN_B>>>();
    scatter_kernel<<<(E_EDGES + 255) / 256, 256>>>(ei);
    aggregate_kernel<<<(N_NODES * 16 + 255) / 256, 256>>>(out);
}

// round 6
// speedup vs baseline: 1.9186x; 1.0275x over previous
#include <cuda_runtime.h>

#define N_NODES 100000
#define E_EDGES 1600000
#define INC 128
#define OUTC 64
#define LRELU_ALPHA 0.2f

#define SCAN_B 1024
#define SCAN_NBLK ((N_NODES + SCAN_B - 1) / SCAN_B)   // 98

// Static device scratch (runtime allocation forbidden)
__device__ __align__(16) float g_h[(size_t)N_NODES * OUTC];   // 25.6 MB
__device__ float g_s[N_NODES];
__device__ float g_t[N_NODES];
__device__ int   g_hist[N_NODES];
__device__ int   g_start[N_NODES];
__device__ int   g_cursor[N_NODES];
__device__ int   g_blocksum[SCAN_NBLK];
__device__ int   g_blockoff[SCAN_NBLK];
__device__ __align__(16) int2 g_sorted[E_EDGES];              // (dst, w) 12.8 MB
__device__ int   g_idx64;

// ---------------------------------------------------------------------------
// Detect index dtype (int64 LE with values < N has all-zero odd words)
// fused with hist zeroing.
// ---------------------------------------------------------------------------
__global__ void detect_zero_kernel(const int* __restrict__ ei32) {
    int i = blockIdx.x * blockDim.x + threadIdx.x;
    if (i < N_NODES) g_hist[i] = 0;
    if (i == 0) {
        int allzero = 1;
#pragma unroll 1
        for (int k = 0; k < 64; ++k)
            if (ei32[2 * k + 1] != 0) { allzero = 0; break; }
        g_idx64 = allzero;
    }
}

// ---------------------------------------------------------------------------
// h = x @ W (W staged in smem), fused s = h.a1, t = h.a2.
// ---------------------------------------------------------------------------
__global__ __launch_bounds__(256) void gemm_kernel(
    const float* __restrict__ x, const float* __restrict__ W,
    const float* __restrict__ a)
{
    __shared__ __align__(16) float sW[INC * OUTC];   // 32 KB
    {
        const float4* Wv = reinterpret_cast<const float4*>(W);
        float4* sWv = reinterpret_cast<float4*>(sW);
#pragma unroll
        for (int i = 0; i < (INC * OUTC) / (256 * 4); ++i)
            sWv[threadIdx.x + i * 256] = Wv[threadIdx.x + i * 256];
    }
    __syncthreads();

    int row = blockIdx.x * blockDim.x + threadIdx.x;
    if (row >= N_NODES) return;

    float acc[OUTC];
#pragma unroll
    for (int c = 0; c < OUTC; ++c) acc[c] = 0.0f;

    const float4* xr = reinterpret_cast<const float4*>(x + (size_t)row * INC);
#pragma unroll 2
    for (int k4 = 0; k4 < INC / 4; ++k4) {
        float4 xv = __ldg(xr + k4);
        float xk[4] = {xv.x, xv.y, xv.z, xv.w};
#pragma unroll
        for (int kk = 0; kk < 4; ++kk) {
            const float4* w4 =
                reinterpret_cast<const float4*>(sW + (k4 * 4 + kk) * OUTC);
#pragma unroll
            for (int c4 = 0; c4 < OUTC / 4; ++c4) {
                float4 wv = w4[c4];
                acc[c4 * 4 + 0] = fmaf(xk[kk], wv.x, acc[c4 * 4 + 0]);
                acc[c4 * 4 + 1] = fmaf(xk[kk], wv.y, acc[c4 * 4 + 1]);
                acc[c4 * 4 + 2] = fmaf(xk[kk], wv.z, acc[c4 * 4 + 2]);
                acc[c4 * 4 + 3] = fmaf(xk[kk], wv.w, acc[c4 * 4 + 3]);
            }
        }
    }

    float s = 0.0f, t = 0.0f;
#pragma unroll
    for (int c = 0; c < OUTC; ++c) {
        s = fmaf(acc[c], __ldg(a + c), s);
        t = fmaf(acc[c], __ldg(a + OUTC + c), t);
    }

    float4* hp = reinterpret_cast<float4*>(g_h + (size_t)row * OUTC);
#pragma unroll
    for (int c4 = 0; c4 < OUTC / 4; ++c4)
        hp[c4] = make_float4(acc[c4 * 4 + 0], acc[c4 * 4 + 1],
                             acc[c4 * 4 + 2], acc[c4 * 4 + 3]);
    g_s[row] = s;
    g_t[row] = t;
}

// ---------------------------------------------------------------------------
// Histogram of src: 4 edges per thread (vector loads for MLP).
// E_EDGES % 4 == 0.
// ---------------------------------------------------------------------------
__global__ __launch_bounds__(256) void hist_kernel(const void* __restrict__ ei)
{
    int q = blockIdx.x * blockDim.x + threadIdx.x;
    if (q >= E_EDGES / 4) return;
    int s0, s1, s2, s3;
    if (g_idx64) {
        const longlong2* p = (const longlong2*)ei;
        longlong2 a = __ldg(p + 2 * q);
        longlong2 b = __ldg(p + 2 * q + 1);
        s0 = (int)a.x; s1 = (int)a.y; s2 = (int)b.x; s3 = (int)b.y;
    } else {
        int4 v = __ldg((const int4*)ei + q);
        s0 = v.x; s1 = v.y; s2 = v.z; s3 = v.w;
    }
    atomicAdd(g_hist + s0, 1);
    atomicAdd(g_hist + s1, 1);
    atomicAdd(g_hist + s2, 1);
    atomicAdd(g_hist + s3, 1);
}

// Scan step 1: per-block exclusive scan + block totals
__global__ __launch_bounds__(SCAN_B) void scan1_kernel()
{
    __shared__ int sh[SCAN_B];
    int tid = threadIdx.x;
    int i = blockIdx.x * SCAN_B + tid;
    int v = (i < N_NODES) ? g_hist[i] : 0;
    sh[tid] = v;
    __syncthreads();
#pragma unroll
    for (int off = 1; off < SCAN_B; off <<= 1) {
        int t = (tid >= off) ? sh[tid - off] : 0;
        __syncthreads();
        sh[tid] += t;
        __syncthreads();
    }
    if (i < N_NODES) g_start[i] = sh[tid] - v;
    if (tid == SCAN_B - 1) g_blocksum[blockIdx.x] = sh[tid];
}

__global__ void scan2_kernel()
{
    int run = 0;
#pragma unroll 1
    for (int b = 0; b < SCAN_NBLK; ++b) {
        g_blockoff[b] = run;
        run += g_blocksum[b];
    }
}

__global__ __launch_bounds__(SCAN_B) void scan3_kernel()
{
    int i = blockIdx.x * SCAN_B + threadIdx.x;
    if (i < N_NODES) {
        int s = g_start[i] + g_blockoff[blockIdx.x];
        g_start[i] = s;
        g_cursor[i] = s;
    }
}

// ---------------------------------------------------------------------------
// Scatter: 2 edges per thread; packed (dst, w) 8-byte store.
// E_EDGES % 2 == 0.
// ---------------------------------------------------------------------------
__global__ __launch_bounds__(256) void scatter_kernel(const void* __restrict__ ei)
{
    int q = blockIdx.x * blockDim.x + threadIdx.x;
    if (q >= E_EDGES / 2) return;
    int src0, src1, dst0, dst1;
    if (g_idx64) {
        const longlong2* p = (const longlong2*)ei;
        longlong2 sv = __ldg(p + q);
        longlong2 dv = __ldg(p + E_EDGES / 2 + q);
        src0 = (int)sv.x; src1 = (int)sv.y;
        dst0 = (int)dv.x; dst1 = (int)dv.y;
    } else {
        const int2* p = (const int2*)ei;
        int2 sv = __ldg(p + q);
        int2 dv = __ldg(p + E_EDGES / 2 + q);
        src0 = sv.x; src1 = sv.y;
        dst0 = dv.x; dst1 = dv.y;
    }

    float z0 = __ldg(g_s + src0) + __ldg(g_t + dst0);
    float z1 = __ldg(g_s + src1) + __ldg(g_t + dst1);
    float w0 = __expf((z0 > 0.0f) ? z0 : LRELU_ALPHA * z0);
    float w1 = __expf((z1 > 0.0f) ? z1 : LRELU_ALPHA * z1);

    int p0 = atomicAdd(g_cursor + src0, 1);
    int p1 = atomicAdd(g_cursor + src1, 1);
    g_sorted[p0] = make_int2(dst0, __float_as_int(w0));
    g_sorted[p1] = make_int2(dst1, __float_as_int(w1));
}

// ---------------------------------------------------------------------------
// Aggregate: 16 lanes per node; gather-only; prefetch next (dst,w);
// finalize + self-loop fused; single write to d_out.
// ---------------------------------------------------------------------------
__global__ __launch_bounds__(256) void aggregate_kernel(float* __restrict__ out)
{
    int gt = blockIdx.x * blockDim.x + threadIdx.x;
    int node = gt >> 4;
    int sub = gt & 15;
    if (node >= N_NODES) return;

    float z = __ldg(g_s + node) + __ldg(g_t + node);
    float wself = __expf((z > 0.0f) ? z : LRELU_ALPHA * z);

    const float4* hn = reinterpret_cast<const float4*>(g_h + (size_t)node * OUTC);
    float4 hv = __ldg(hn + sub);
    float4 acc = make_float4(wself * hv.x, wself * hv.y, wself * hv.z, wself * hv.w);
    float es = wself;

    int base = __ldg(g_start + node);
    int cnt = __ldg(g_hist + node);

    int2 cur;
    if (cnt > 0) cur = __ldg(g_sorted + base);
#pragma unroll 1
    for (int j = 0; j < cnt; ++j) {
        int dst = cur.x;
        float w = __int_as_float(cur.y);
        if (j + 1 < cnt) cur = __ldg(g_sorted + base + j + 1);
        const float4* hd = reinterpret_cast<const float4*>(g_h + (size_t)dst * OUTC);
        float4 v = __ldg(hd + sub);
        acc.x = fmaf(w, v.x, acc.x);
        acc.y = fmaf(w, v.y, acc.y);
        acc.z = fmaf(w, v.z, acc.z);
        acc.w = fmaf(w, v.w, acc.w);
        es += w;
    }

    float inv = 1.0f / es;
    reinterpret_cast<float4*>(out)[(size_t)node * 16 + sub] =
        make_float4(acc.x * inv, acc.y * inv, acc.z * inv, acc.w * inv);
}

// ---------------------------------------------------------------------------
extern "C" void kernel_launch(void* const* d_in, const int* in_sizes, int n_in,
                              void* d_out, int out_size)
{
    const float* x = (const float*)d_in[0];
    const float* W = (const float*)d_in[1];
    const float* a = (const float*)d_in[2];
    const void*  ei = d_in[3];
    float* out = (float*)d_out;

    detect_zero_kernel<<<(N_NODES + 255) / 256, 256>>>((const int*)ei);
    gemm_kernel<<<(N_NODES + 255) / 256, 256>>>(x, W, a);
    hist_kernel<<<(E_EDGES / 4 + 255) / 256, 256>>>(ei);
    scan1_kernel<<<SCAN_NBLK, SCAN_B>>>();
    scan2_kernel<<<1, 1>>>();
    scan3_kernel<<<SCAN_NBLK, SCAN_B>>>();
    scatter_kernel<<<(E_EDGES / 2 + 255) / 256, 256>>>(ei);
    aggregate_kernel<<<(N_NODES * 16 + 255) / 256, 256>>>(out);
}